// round 3
// baseline (speedup 1.0000x reference)
#include <cuda_runtime.h>
#include <math.h>

#define NE 640000
#define NN 20000
#define NB 8
#define D1 136
#define D2 128
#define D3 128
#define LAT 64

// ---- scratch (static device globals; no allocations) ----
__device__ __align__(16) float g_ef[(size_t)NE * LAT];      // 163.84 MB
__device__ float g_score[NE];
__device__ __align__(16) float g_pooled[(size_t)NN * LAT];  // 5.12 MB
__device__ unsigned g_umax;
__device__ float g_sumexp;

__device__ __forceinline__ float wsum(float v) {
#pragma unroll
    for (int o = 16; o; o >>= 1) v += __shfl_xor_sync(0xffffffffu, v, o);
    return v;
}

// order-preserving float<->uint key for atomicMax over signed floats
__device__ __forceinline__ unsigned enc_key(float f) {
    int b = __float_as_int(f);
    return (b >= 0) ? ((unsigned)b | 0x80000000u) : ~(unsigned)b;
}
__device__ __forceinline__ float dec_key(unsigned u) {
    int b = (u & 0x80000000u) ? (int)(u ^ 0x80000000u) : ~(int)u;
    return __int_as_float(b);
}

__global__ void k_init() {
    int i = blockIdx.x * blockDim.x + threadIdx.x;
    const int n = NN * LAT;
    for (; i < n; i += gridDim.x * blockDim.x) g_pooled[i] = 0.f;
    if (blockIdx.x == 0 && threadIdx.x == 0) { g_umax = 0u; g_sumexp = 0.f; }
}

// ---------------- K1: ef = LN1(edge_in) @ W1 + b1 ; score ----------------
__global__ void __launch_bounds__(256) k_edge1(
    const int* __restrict__ eidx, const float* __restrict__ elen,
    const float* __restrict__ nattr,
    const float* __restrict__ ln1g, const float* __restrict__ ln1b,
    const float* __restrict__ W1, const float* __restrict__ b1,
    const float* __restrict__ ln2g, const float* __restrict__ ln2b,
    const float* __restrict__ W2, const float* __restrict__ b2)
{
    __shared__ __align__(16) float sW1[D1 * LAT];
    __shared__ float sg1[D1], sb1[D1];
    __shared__ float sbias[LAT];
    __shared__ float sg2[D2], sb2[D2], sW2[D2];
    __shared__ __align__(16) float sx[8][D1];
    __shared__ float smax[8];

    const int tid = threadIdx.x;
    for (int i = tid; i < D1 * LAT; i += 256) sW1[i] = W1[i];
    for (int i = tid; i < D1; i += 256) { sg1[i] = ln1g[i]; sb1[i] = ln1b[i]; }
    for (int i = tid; i < D2; i += 256) { sg2[i] = ln2g[i]; sb2[i] = ln2b[i]; sW2[i] = W2[i]; }
    for (int i = tid; i < LAT; i += 256) sbias[i] = b1[i];
    __syncthreads();

    const int w = tid >> 5, lane = tid & 31;
    const int i0 = 2 * lane;
    const float b2v = b2[0];
    const float2* sW1v = (const float2*)sW1;
    float runmax = -3.4e38f;

    int e = blockIdx.x * 8 + w;
    const int stride = gridDim.x * 8;

    for (; e < NE; e += stride) {
        const int c = eidx[e];
        const int nn = eidx[NE + e];
        const float2 ac = ((const float2*)(nattr + (size_t)c * LAT))[lane];
        const float2 an = ((const float2*)(nattr + (size_t)nn * LAT))[lane];
        const float r = elen[e];

        float rb = 0.f;
        {
            float t = r * (1.0f / 6.0f);
            float t2 = t * t, t6 = t2 * t2 * t2;
            float ct = tanhf(1.0f - t6);
            float cut = ct * ct * ct;
            rb = 0.57735026918962576f * sinf((float)(lane + 1) * 0.5235987755982988f * r) / r * cut;
        }

        float ls = ac.x + ac.y + an.x + an.y;
        float lss = ac.x * ac.x + ac.y * ac.y + an.x * an.x + an.y * an.y;
        if (lane < 8) { ls += rb; lss += rb * rb; }
        const float S = wsum(ls), SS = wsum(lss);
        const float mean = S * (1.0f / 136.0f);
        const float var = SS * (1.0f / 136.0f) - mean * mean;
        const float rinv = rsqrtf(var + 1e-5f);

        sx[w][i0]          = (ac.x - mean) * rinv * sg1[i0]          + sb1[i0];
        sx[w][i0 + 1]      = (ac.y - mean) * rinv * sg1[i0 + 1]      + sb1[i0 + 1];
        sx[w][64 + i0]     = (an.x - mean) * rinv * sg1[64 + i0]     + sb1[64 + i0];
        sx[w][64 + i0 + 1] = (an.y - mean) * rinv * sg1[64 + i0 + 1] + sb1[64 + i0 + 1];
        if (lane < 8) sx[w][128 + lane] = (rb - mean) * rinv * sg1[128 + lane] + sb1[128 + lane];
        __syncwarp();

        float acc0 = sbias[i0], acc1 = sbias[i0 + 1];
#pragma unroll 8
        for (int k = 0; k < D1; k++) {
            const float xk = sx[w][k];
            const float2 wv = sW1v[k * 32 + lane];
            acc0 = fmaf(xk, wv.x, acc0);
            acc1 = fmaf(xk, wv.y, acc1);
        }
        ((float2*)g_ef)[(size_t)e * 32 + lane] = make_float2(acc0, acc1);

        // score = LN2([ef, a_c]) . W2 + b2
        float s2 = acc0 + acc1 + ac.x + ac.y;
        float ss2 = acc0 * acc0 + acc1 * acc1 + ac.x * ac.x + ac.y * ac.y;
        const float T = wsum(s2), TT = wsum(ss2);
        const float m2 = T * (1.0f / 128.0f);
        const float v2 = TT * (1.0f / 128.0f) - m2 * m2;
        const float ri2 = rsqrtf(v2 + 1e-5f);
        float sc = ((acc0 - m2) * ri2 * sg2[i0]          + sb2[i0])          * sW2[i0]
                 + ((acc1 - m2) * ri2 * sg2[i0 + 1]      + sb2[i0 + 1])      * sW2[i0 + 1]
                 + ((ac.x - m2) * ri2 * sg2[64 + i0]     + sb2[64 + i0])     * sW2[64 + i0]
                 + ((ac.y - m2) * ri2 * sg2[64 + i0 + 1] + sb2[64 + i0 + 1]) * sW2[64 + i0 + 1];
        sc = wsum(sc) + b2v;
        if (lane == 0) g_score[e] = sc;
        runmax = fmaxf(runmax, sc);
        __syncwarp();   // protect sx against next-iteration writes
    }
    if (lane == 0) smax[w] = runmax;
    __syncthreads();
    if (tid == 0) {
        float m = smax[0];
        for (int i = 1; i < 8; i++) m = fmaxf(m, smax[i]);
        atomicMax(&g_umax, enc_key(m));
    }
}

// ---------------- K2: sum of exp(score - max) ----------------
__global__ void __launch_bounds__(256) k_sumexp() {
    __shared__ float sred[256];
    const float mx = dec_key(g_umax);
    float v = 0.f;
    for (int i = blockIdx.x * 256 + threadIdx.x; i < NE; i += gridDim.x * 256)
        v += expf(g_score[i] - mx);
    sred[threadIdx.x] = v;
    __syncthreads();
    for (int o = 128; o; o >>= 1) {
        if (threadIdx.x < o) sred[threadIdx.x] += sred[threadIdx.x + o];
        __syncthreads();
    }
    if (threadIdx.x == 0) atomicAdd(&g_sumexp, sred[0]);
}

// ---------------- K3: pooled[ec] += attn * ef ----------------
__global__ void __launch_bounds__(256) k_scatter(const int* __restrict__ eidx) {
    const int e = blockIdx.x * 8 + (threadIdx.x >> 5);
    if (e >= NE) return;
    const int lane = threadIdx.x & 31;
    const float mx = dec_key(g_umax);
    const float inv = 1.0f / g_sumexp;
    const float wgt = expf(g_score[e] - mx) * inv;
    const int c = eidx[e];
    const float2 ef = ((const float2*)g_ef)[(size_t)e * 32 + lane];
    atomicAdd(&g_pooled[(size_t)c * LAT + 2 * lane],     wgt * ef.x);
    atomicAdd(&g_pooled[(size_t)c * LAT + 2 * lane + 1], wgt * ef.y);
}

// ---------------- K4: upd = LN3([ef, pooled[ec]])@W3 + b3 ; gate ; out ----------------
extern __shared__ float dyn4[];
__global__ void __launch_bounds__(256) k_edge2(
    const int* __restrict__ eidx, const float* __restrict__ elen,
    const float* __restrict__ ln3g, const float* __restrict__ ln3b,
    const float* __restrict__ W3, const float* __restrict__ b3,
    const float* __restrict__ fW1, const float* __restrict__ fW2,
    const float* __restrict__ resp, float* __restrict__ out)
{
    float* sW3 = dyn4;               // 8192 floats
    float* sF2 = sW3 + D3 * LAT;     // 8192
    float* sF1 = sF2 + D3 * LAT;     // 2048
    float* sg3 = sF1 + NB * 256;     // 128
    float* sb3 = sg3 + D3;           // 128
    float* sbb = sb3 + D3;           // 64
    float* sxa = sbb + LAT;          // 8*128
    float* sta = sxa + 8 * D3;       // 8*128

    const int tid = threadIdx.x;
    for (int i = tid; i < D3 * LAT; i += 256) { sW3[i] = W3[i]; sF2[i] = fW2[i]; }
    for (int i = tid; i < NB * 256; i += 256) sF1[i] = fW1[i];
    for (int i = tid; i < D3; i += 256) { sg3[i] = ln3g[i]; sb3[i] = ln3b[i]; }
    for (int i = tid; i < LAT; i += 256) sbb[i] = b3[i];
    __syncthreads();

    const float p = resp[0];
    const float uc = 1.0f / (1.0f + expf(-p));
    const float cc = rsqrtf(uc * uc + 1.0f);
    const float sscale = uc * cc * (1.0f + cc + cc * cc);   // 3 recycles collapsed

    const int w = tid >> 5, lane = tid & 31;
    const int i0 = 2 * lane;
    float* mx = sxa + w * D3;
    float* mt = sta + w * D3;
    const float2* sW3v = (const float2*)sW3;
    const float2* sF2v = (const float2*)sF2;

    int e = blockIdx.x * 8 + w;
    const int stride = gridDim.x * 8;

    for (; e < NE; e += stride) {
        const int c = eidx[e];
        const float2 ef = ((const float2*)g_ef)[(size_t)e * 32 + lane];
        const float2 pc = ((const float2*)g_pooled)[(size_t)c * 32 + lane];

        float ls = ef.x + ef.y + pc.x + pc.y;
        float lss = ef.x * ef.x + ef.y * ef.y + pc.x * pc.x + pc.y * pc.y;
        const float S = wsum(ls), SS = wsum(lss);
        const float mean = S * (1.0f / 128.0f);
        const float var = SS * (1.0f / 128.0f) - mean * mean;
        const float ri = rsqrtf(var + 1e-5f);

        mx[i0]          = (ef.x - mean) * ri * sg3[i0]          + sb3[i0];
        mx[i0 + 1]      = (ef.y - mean) * ri * sg3[i0 + 1]      + sb3[i0 + 1];
        mx[64 + i0]     = (pc.x - mean) * ri * sg3[64 + i0]     + sb3[64 + i0];
        mx[64 + i0 + 1] = (pc.y - mean) * ri * sg3[64 + i0 + 1] + sb3[64 + i0 + 1];

        // FiLM: rbf -> t = silu(a)*g
        const float r = elen[e];
        float rbl;
        {
            float t = r * (1.0f / 6.0f);
            float t2 = t * t, t6 = t2 * t2 * t2;
            float ct = tanhf(1.0f - t6);
            float cut = ct * ct * ct;
            rbl = 0.57735026918962576f * sinf((float)(lane + 1) * 0.5235987755982988f * r) / r * cut;
        }
        float rbv[8];
#pragma unroll
        for (int k = 0; k < 8; k++) rbv[k] = __shfl_sync(0xffffffffu, rbl, k);
#pragma unroll
        for (int q = 0; q < 4; q++) {
            const int idx = (q & 1) + ((q >> 1) << 6) + i0;
            float a = 0.f, g = 0.f;
#pragma unroll
            for (int k = 0; k < 8; k++) {
                a = fmaf(rbv[k], sF1[k * 256 + idx], a);
                g = fmaf(rbv[k], sF1[k * 256 + 128 + idx], g);
            }
            const float sil = a / (1.0f + expf(-a));
            mt[idx] = sil * g;
        }
        __syncwarp();

        float u0 = sbb[i0], u1 = sbb[i0 + 1];
        float q0 = 0.f, q1 = 0.f;
#pragma unroll 8
        for (int k = 0; k < D3; k++) {
            const float xk = mx[k];
            const float tk = mt[k];
            const float2 w3 = sW3v[k * 32 + lane];
            const float2 f2 = sF2v[k * 32 + lane];
            u0 = fmaf(xk, w3.x, u0); u1 = fmaf(xk, w3.y, u1);
            q0 = fmaf(tk, f2.x, q0); q1 = fmaf(tk, f2.y, q1);
        }
        const float g0 = 1.0f / (1.0f + expf(-q0));
        const float g1 = 1.0f / (1.0f + expf(-q1));
        ((float2*)out)[(size_t)e * 32 + lane] = make_float2(u0 * g0 * sscale, u1 * g1 * sscale);
        __syncwarp();
    }
}

#define K4_SMEM 83200

extern "C" void kernel_launch(void* const* d_in, const int* in_sizes, int n_in,
                              void* d_out, int out_size) {
    const int*   eidx  = (const int*)d_in[0];
    const float* elen  = (const float*)d_in[1];
    const float* nattr = (const float*)d_in[2];
    const float* ln1g  = (const float*)d_in[3];
    const float* ln1b  = (const float*)d_in[4];
    const float* W1    = (const float*)d_in[5];
    const float* b1    = (const float*)d_in[6];
    const float* ln2g  = (const float*)d_in[7];
    const float* ln2b  = (const float*)d_in[8];
    const float* W2    = (const float*)d_in[9];
    const float* b2    = (const float*)d_in[10];
    const float* ln3g  = (const float*)d_in[11];
    const float* ln3b  = (const float*)d_in[12];
    const float* W3    = (const float*)d_in[13];
    const float* b3    = (const float*)d_in[14];
    const float* fW1   = (const float*)d_in[15];
    const float* fW2   = (const float*)d_in[16];
    const float* resp  = (const float*)d_in[17];
    float* out = (float*)d_out;

    cudaFuncSetAttribute(k_edge2, cudaFuncAttributeMaxDynamicSharedMemorySize, K4_SMEM);

    k_init<<<5120, 256>>>();
    k_edge1<<<592, 256>>>(eidx, elen, nattr, ln1g, ln1b, W1, b1, ln2g, ln2b, W2, b2);
    k_sumexp<<<592, 256>>>();
    k_scatter<<<(NE + 7) / 8, 256>>>(eidx);
    k_edge2<<<296, 256, K4_SMEM>>>(eidx, elen, ln3g, ln3b, W3, b3, fW1, fW2, resp, out);
}

// round 4
// speedup vs baseline: 2.6102x; 2.6102x over previous
#include <cuda_runtime.h>
#include <math.h>

#define NE 640000
#define NN 20000
#define NB 8
#define D1 136
#define LAT 64
#define TBL 8192

// ---- scratch (static device globals; no allocations) ----
__device__ __align__(16) float g_ef[(size_t)NE * LAT];       // 163.84 MB
__device__ float g_score[NE];
__device__ __align__(16) float g_pooled[(size_t)NN * LAT];   // 5.12 MB
__device__ __align__(16) float g_gate[(TBL + 1) * LAT];      // 2.1 MB
__device__ unsigned g_umax;
__device__ float g_sumexp;

// ---- helpers ----
__device__ __forceinline__ float wsum(float v) {
#pragma unroll
    for (int o = 16; o; o >>= 1) v += __shfl_xor_sync(0xffffffffu, v, o);
    return v;
}
__device__ __forceinline__ unsigned enc_key(float f) {
    int b = __float_as_int(f);
    return (b >= 0) ? ((unsigned)b | 0x80000000u) : ~(unsigned)b;
}
__device__ __forceinline__ float dec_key(unsigned u) {
    int b = (u & 0x80000000u) ? (int)(u ^ 0x80000000u) : ~(int)u;
    return __int_as_float(b);
}
__device__ __forceinline__ unsigned s2u(const void* p) {
    return (unsigned)__cvta_generic_to_shared(p);
}

// packed fp32x2 FMA: d = a*b + d   (bitwise == two fmaf)
#define FMA2(d, a, b) \
    asm("fma.rn.f32x2 %0, %1, %2, %0;" : "+l"(d) : "l"(a), "l"(b))
// 16B shared load into two 64-bit packed regs
#define LDSV2(lo, hi, addr) \
    asm volatile("ld.shared.v2.b64 {%0,%1},[%2];" : "=l"(lo), "=l"(hi) : "r"(addr))
#define PACK2(d, lo, hi) \
    asm("mov.b64 %0, {%1, %2};" : "=l"(d) : "r"(__float_as_int(lo)), "r"(__float_as_int(hi)))
#define UNPACK2(lo, hi, s) \
    do { unsigned _a, _b; asm("mov.b64 {%0,%1}, %2;" : "=r"(_a), "=r"(_b) : "l"(s)); \
         lo = __int_as_float(_a); hi = __int_as_float(_b); } while (0)

__device__ __forceinline__ float cutoff3(float r) {
    float t = r * (1.0f / 6.0f);
    float t2 = t * t, t6 = t2 * t2 * t2;
    float ct = tanhf(1.0f - t6);
    return ct * ct * ct;
}

__global__ void k_init() {
    int i = blockIdx.x * blockDim.x + threadIdx.x;
    const int n = NN * LAT;
    for (; i < n; i += gridDim.x * blockDim.x) g_pooled[i] = 0.f;
    if (blockIdx.x == 0 && threadIdx.x == 0) { g_umax = 0u; g_sumexp = 0.f; }
}

// ---------------- gate table: gate(r) = sigmoid((silu(a)*g) @ fW2) ----------------
__global__ void __launch_bounds__(256) k_gate(const float* __restrict__ fW1,
                                              const float* __restrict__ fW2) {
    __shared__ float st[8][128];
    const int w = threadIdx.x >> 5, lane = threadIdx.x & 31;
    const int p = blockIdx.x * 8 + w;
    if (p > TBL) return;
    const float r = 0.5f + (5.5f / (float)TBL) * (float)p;
    const float cut = cutoff3(r);
    float rb[NB];
#pragma unroll
    for (int n = 0; n < NB; n++)
        rb[n] = 0.57735026918962576f * sinf((float)(n + 1) * 0.5235987755982988f * r) / r * cut;
#pragma unroll
    for (int j = 0; j < 4; j++) {
        const int k = lane + 32 * j;
        float a = 0.f, g = 0.f;
#pragma unroll
        for (int n = 0; n < NB; n++) {
            a = fmaf(rb[n], fW1[n * 256 + k], a);
            g = fmaf(rb[n], fW1[n * 256 + 128 + k], g);
        }
        st[w][k] = a / (1.0f + expf(-a)) * g;
    }
    __syncwarp();
    float q0 = 0.f, q1 = 0.f;
#pragma unroll 8
    for (int k = 0; k < 128; k++) {
        const float2 f2 = ((const float2*)fW2)[k * 32 + lane];
        const float tv = st[w][k];
        q0 = fmaf(tv, f2.x, q0);
        q1 = fmaf(tv, f2.y, q1);
    }
    ((float2*)g_gate)[p * 32 + lane] =
        make_float2(1.0f / (1.0f + expf(-q0)), 1.0f / (1.0f + expf(-q1)));
}

// ---------------- K1: ef = LN1(edge_in) @ W1 + b1 ; score ----------------
// smem: sW1q float4[68*32]=34816B | sxq float4[8w*8e*68]=69632B | params 2624B = 107072B
#define K1_SMEM 107072
__global__ void __launch_bounds__(256, 2) k_edge1(
    const int* __restrict__ eidx, const float* __restrict__ elen,
    const float* __restrict__ nattr,
    const float* __restrict__ ln1g, const float* __restrict__ ln1b,
    const float* __restrict__ W1, const float* __restrict__ b1,
    const float* __restrict__ ln2g, const float* __restrict__ ln2b,
    const float* __restrict__ W2, const float* __restrict__ b2)
{
    extern __shared__ __align__(16) char dynsm[];
    float4* sW1q = (float4*)dynsm;
    float4* sxq  = (float4*)(dynsm + 34816);
    float* sg1 = (float*)(dynsm + 104448);
    float* sb1 = sg1 + 136;
    float* sg2 = sb1 + 136;
    float* sb2 = sg2 + 128;
    float* sW2 = sb2 + 128;
    __shared__ float smax_s[8];

    const int tid = threadIdx.x;
    // weight dup-pair layout: sW1q[kk*32+l] = {W1[2kk][2l],W1[2kk][2l+1],W1[2kk+1][2l],W1[2kk+1][2l+1]}
    for (int i = tid; i < 68 * 32; i += 256) {
        const int kk = i >> 5, l = i & 31;
        float4 v;
        v.x = W1[(2 * kk) * 64 + 2 * l];
        v.y = W1[(2 * kk) * 64 + 2 * l + 1];
        v.z = W1[(2 * kk + 1) * 64 + 2 * l];
        v.w = W1[(2 * kk + 1) * 64 + 2 * l + 1];
        sW1q[i] = v;
    }
    for (int i = tid; i < D1; i += 256) { sg1[i] = ln1g[i]; sb1[i] = ln1b[i]; }
    for (int i = tid; i < 128; i += 256) { sg2[i] = ln2g[i]; sb2[i] = ln2b[i]; sW2[i] = W2[i]; }
    __syncthreads();

    const int w = tid >> 5, lane = tid & 31;
    const float b2v = b2[0];
    const float2 b1v = ((const float2*)b1)[lane];
    unsigned long long bias2; PACK2(bias2, b1v.x, b1v.y);
    const float2* nat2 = (const float2*)nattr;

    const unsigned wq_u = s2u(sW1q) + lane * 16;
    const unsigned sx_u = s2u(sxq);
    unsigned xb[8];
#pragma unroll
    for (int e = 0; e < 8; e++) xb[e] = sx_u + (unsigned)((w * 8 + e) * 68) * 16;

    float runmax = -3.4e38f;

    for (int g0 = blockIdx.x * 64 + w * 8; g0 < NE; g0 += gridDim.x * 64) {
        // ---- prefetch 8 edges ----
        int cI[8], nI[8];
        float rr_[8];
#pragma unroll
        for (int e = 0; e < 8; e++) {
            cI[e] = eidx[g0 + e];
            nI[e] = eidx[NE + g0 + e];
            rr_[e] = elen[g0 + e];
        }
        float2 acv[8], anv[8];
#pragma unroll
        for (int e = 0; e < 8; e++) {
            acv[e] = nat2[(size_t)cI[e] * 32 + lane];
            anv[e] = nat2[(size_t)nI[e] * 32 + lane];
        }
        // ---- LN1 + dup-pair store ----
#pragma unroll
        for (int e = 0; e < 8; e++) {
            const float2 ac = acv[e], an = anv[e];
            const float r = rr_[e];
            const float rb = 0.57735026918962576f *
                sinf((float)(lane + 1) * 0.5235987755982988f * r) / r * cutoff3(r);
            float ls = ac.x + ac.y + an.x + an.y;
            float lss = ac.x * ac.x + ac.y * ac.y + an.x * an.x + an.y * an.y;
            if (lane < 8) { ls += rb; lss += rb * rb; }
            const float S = wsum(ls), SS = wsum(lss);
            const float mean = S * (1.0f / 136.0f);
            const float var = SS * (1.0f / 136.0f) - mean * mean;
            const float ri = rsqrtf(var + 1e-5f);
            const int eb = (w * 8 + e) * 68;
            const float x0 = (ac.x - mean) * ri * sg1[2 * lane] + sb1[2 * lane];
            const float x1 = (ac.y - mean) * ri * sg1[2 * lane + 1] + sb1[2 * lane + 1];
            sxq[eb + lane] = make_float4(x0, x0, x1, x1);
            const float y0 = (an.x - mean) * ri * sg1[64 + 2 * lane] + sb1[64 + 2 * lane];
            const float y1 = (an.y - mean) * ri * sg1[64 + 2 * lane + 1] + sb1[64 + 2 * lane + 1];
            sxq[eb + 32 + lane] = make_float4(y0, y0, y1, y1);
            if (lane < 8) {
                const float z = (rb - mean) * ri * sg1[128 + lane] + sb1[128 + lane];
                ((float2*)(sxq + eb + 64))[lane] = make_float2(z, z);
            }
        }
        __syncwarp();

        // ---- GEMV: 8 edges, f32x2 packed ----
        unsigned long long acc[8];
#pragma unroll
        for (int e = 0; e < 8; e++) acc[e] = bias2;
#pragma unroll 4
        for (int kk = 0; kk < 68; kk++) {
            unsigned long long w01, w23;
            LDSV2(w01, w23, wq_u + kk * 512);
#pragma unroll
            for (int e = 0; e < 8; e++) {
                unsigned long long x01, x23;
                LDSV2(x01, x23, xb[e] + kk * 16);
                FMA2(acc[e], x01, w01);
                FMA2(acc[e], x23, w23);
            }
        }

        // ---- score + store ef ----
#pragma unroll
        for (int e = 0; e < 8; e++) {
            float e0, e1;
            UNPACK2(e0, e1, acc[e]);
            const float2 a = acv[e];
            float s2 = e0 + e1 + a.x + a.y;
            float ss2 = e0 * e0 + e1 * e1 + a.x * a.x + a.y * a.y;
            const float T = wsum(s2), TT = wsum(ss2);
            const float m2 = T * (1.0f / 128.0f);
            const float v2 = TT * (1.0f / 128.0f) - m2 * m2;
            const float ri2 = rsqrtf(v2 + 1e-5f);
            float sc = ((e0 - m2) * ri2 * sg2[2 * lane] + sb2[2 * lane]) * sW2[2 * lane]
                     + ((e1 - m2) * ri2 * sg2[2 * lane + 1] + sb2[2 * lane + 1]) * sW2[2 * lane + 1]
                     + ((a.x - m2) * ri2 * sg2[64 + 2 * lane] + sb2[64 + 2 * lane]) * sW2[64 + 2 * lane]
                     + ((a.y - m2) * ri2 * sg2[64 + 2 * lane + 1] + sb2[64 + 2 * lane + 1]) * sW2[64 + 2 * lane + 1];
            sc = wsum(sc) + b2v;
            if (lane == 0) g_score[g0 + e] = sc;
            runmax = fmaxf(runmax, sc);
            ((float2*)g_ef)[(size_t)(g0 + e) * 32 + lane] = make_float2(e0, e1);
        }
        __syncwarp();
    }
    if (lane == 0) smax_s[w] = runmax;
    __syncthreads();
    if (tid == 0) {
        float m = smax_s[0];
        for (int i = 1; i < 8; i++) m = fmaxf(m, smax_s[i]);
        atomicMax(&g_umax, enc_key(m));
    }
}

// ---------------- K2: sum of exp(score - max) ----------------
__global__ void __launch_bounds__(256) k_sumexp() {
    __shared__ float sred[256];
    const float mx = dec_key(g_umax);
    float v = 0.f;
    for (int i = blockIdx.x * 256 + threadIdx.x; i < NE; i += gridDim.x * 256)
        v += expf(g_score[i] - mx);
    sred[threadIdx.x] = v;
    __syncthreads();
    for (int o = 128; o; o >>= 1) {
        if (threadIdx.x < o) sred[threadIdx.x] += sred[threadIdx.x + o];
        __syncthreads();
    }
    if (threadIdx.x == 0) atomicAdd(&g_sumexp, sred[0]);
}

// ---------------- K3: pooled[ec] += attn * ef ----------------
__global__ void __launch_bounds__(256) k_scatter(const int* __restrict__ eidx) {
    const int e = blockIdx.x * 8 + (threadIdx.x >> 5);
    if (e >= NE) return;
    const int lane = threadIdx.x & 31;
    const float mx = dec_key(g_umax);
    const float inv = 1.0f / g_sumexp;
    const float wgt = expf(g_score[e] - mx) * inv;
    const int c = eidx[e];
    const float2 ef = ((const float2*)g_ef)[(size_t)e * 32 + lane];
    atomicAdd(&g_pooled[(size_t)c * LAT + 2 * lane], wgt * ef.x);
    atomicAdd(&g_pooled[(size_t)c * LAT + 2 * lane + 1], wgt * ef.y);
}

// ---------------- K4: upd = LN3([ef, pooled[ec]]) @ W3 + b3 ; table gate ; out ----------------
// smem: sW3q float4[64*32]=32768B | sxq float4[8*8*64]=65536B | params 1024B = 99328B
#define K4_SMEM 99328
__global__ void __launch_bounds__(256, 2) k_edge2(
    const int* __restrict__ eidx, const float* __restrict__ elen,
    const float* __restrict__ ln3g, const float* __restrict__ ln3b,
    const float* __restrict__ W3, const float* __restrict__ b3,
    const float* __restrict__ resp, float* __restrict__ out)
{
    extern __shared__ __align__(16) char dynsm[];
    float4* sW3q = (float4*)dynsm;
    float4* sxq  = (float4*)(dynsm + 32768);
    float* sg3 = (float*)(dynsm + 98304);
    float* sb3 = sg3 + 128;

    const int tid = threadIdx.x;
    for (int i = tid; i < 64 * 32; i += 256) {
        const int kk = i >> 5, l = i & 31;
        float4 v;
        v.x = W3[(2 * kk) * 64 + 2 * l];
        v.y = W3[(2 * kk) * 64 + 2 * l + 1];
        v.z = W3[(2 * kk + 1) * 64 + 2 * l];
        v.w = W3[(2 * kk + 1) * 64 + 2 * l + 1];
        sW3q[i] = v;
    }
    for (int i = tid; i < 128; i += 256) { sg3[i] = ln3g[i]; sb3[i] = ln3b[i]; }
    __syncthreads();

    const float p = resp[0];
    const float uc = 1.0f / (1.0f + expf(-p));
    const float cc = rsqrtf(uc * uc + 1.0f);
    const float ss = uc * cc * (1.0f + cc + cc * cc);   // 3 recycles collapsed

    const int w = tid >> 5, lane = tid & 31;
    const float2 b3v = ((const float2*)b3)[lane];
    unsigned long long bias2; PACK2(bias2, b3v.x, b3v.y);

    const unsigned wq_u = s2u(sW3q) + lane * 16;
    const unsigned sx_u = s2u(sxq);
    unsigned xb[8];
#pragma unroll
    for (int e = 0; e < 8; e++) xb[e] = sx_u + (unsigned)((w * 8 + e) * 64) * 16;

    for (int g0 = blockIdx.x * 64 + w * 8; g0 < NE; g0 += gridDim.x * 64) {
        // ---- prefetch ----
        int cI[8];
        float rr_[8];
#pragma unroll
        for (int e = 0; e < 8; e++) { cI[e] = eidx[g0 + e]; rr_[e] = elen[g0 + e]; }
        float2 efv[8], pcv[8];
#pragma unroll
        for (int e = 0; e < 8; e++) {
            efv[e] = ((const float2*)g_ef)[(size_t)(g0 + e) * 32 + lane];
            pcv[e] = ((const float2*)g_pooled)[(size_t)cI[e] * 32 + lane];
        }
        // ---- LN3 + dup-pair store ----
#pragma unroll
        for (int e = 0; e < 8; e++) {
            const float2 ef = efv[e], pc = pcv[e];
            float ls = ef.x + ef.y + pc.x + pc.y;
            float lss = ef.x * ef.x + ef.y * ef.y + pc.x * pc.x + pc.y * pc.y;
            const float S = wsum(ls), SS = wsum(lss);
            const float mean = S * (1.0f / 128.0f);
            const float var = SS * (1.0f / 128.0f) - mean * mean;
            const float ri = rsqrtf(var + 1e-5f);
            const int eb = (w * 8 + e) * 64;
            const float x0 = (ef.x - mean) * ri * sg3[2 * lane] + sb3[2 * lane];
            const float x1 = (ef.y - mean) * ri * sg3[2 * lane + 1] + sb3[2 * lane + 1];
            sxq[eb + lane] = make_float4(x0, x0, x1, x1);
            const float y0 = (pc.x - mean) * ri * sg3[64 + 2 * lane] + sb3[64 + 2 * lane];
            const float y1 = (pc.y - mean) * ri * sg3[64 + 2 * lane + 1] + sb3[64 + 2 * lane + 1];
            sxq[eb + 32 + lane] = make_float4(y0, y0, y1, y1);
        }
        __syncwarp();

        // ---- GEMV W3 ----
        unsigned long long acc[8];
#pragma unroll
        for (int e = 0; e < 8; e++) acc[e] = bias2;
#pragma unroll 4
        for (int kk = 0; kk < 64; kk++) {
            unsigned long long w01, w23;
            LDSV2(w01, w23, wq_u + kk * 512);
#pragma unroll
            for (int e = 0; e < 8; e++) {
                unsigned long long x01, x23;
                LDSV2(x01, x23, xb[e] + kk * 16);
                FMA2(acc[e], x01, w01);
                FMA2(acc[e], x23, w23);
            }
        }

        // ---- gate via table lerp + output ----
        float2 glo[8], ghi[8], fr;
        float frac[8];
#pragma unroll
        for (int e = 0; e < 8; e++) {
            float u = (rr_[e] - 0.5f) * ((float)TBL / 5.5f);
            u = fminf(fmaxf(u, 0.f), (float)TBL - 0.001f);
            const int i = (int)u;
            frac[e] = u - (float)i;
            glo[e] = ((const float2*)g_gate)[i * 32 + lane];
            ghi[e] = ((const float2*)g_gate)[(i + 1) * 32 + lane];
        }
        (void)fr;
#pragma unroll
        for (int e = 0; e < 8; e++) {
            float u0, u1;
            UNPACK2(u0, u1, acc[e]);
            const float ga = fmaf(frac[e], ghi[e].x - glo[e].x, glo[e].x);
            const float gb = fmaf(frac[e], ghi[e].y - glo[e].y, glo[e].y);
            ((float2*)out)[(size_t)(g0 + e) * 32 + lane] =
                make_float2(u0 * ga * ss, u1 * gb * ss);
        }
        __syncwarp();
    }
}

extern "C" void kernel_launch(void* const* d_in, const int* in_sizes, int n_in,
                              void* d_out, int out_size) {
    const int*   eidx  = (const int*)d_in[0];
    const float* elen  = (const float*)d_in[1];
    const float* nattr = (const float*)d_in[2];
    const float* ln1g  = (const float*)d_in[3];
    const float* ln1b  = (const float*)d_in[4];
    const float* W1    = (const float*)d_in[5];
    const float* b1    = (const float*)d_in[6];
    const float* ln2g  = (const float*)d_in[7];
    const float* ln2b  = (const float*)d_in[8];
    const float* W2    = (const float*)d_in[9];
    const float* b2    = (const float*)d_in[10];
    const float* ln3g  = (const float*)d_in[11];
    const float* ln3b  = (const float*)d_in[12];
    const float* W3    = (const float*)d_in[13];
    const float* b3    = (const float*)d_in[14];
    const float* fW1   = (const float*)d_in[15];
    const float* fW2   = (const float*)d_in[16];
    const float* resp  = (const float*)d_in[17];
    float* out = (float*)d_out;

    static int once = 0;
    if (!once) {
        cudaFuncSetAttribute(k_edge1, cudaFuncAttributeMaxDynamicSharedMemorySize, K1_SMEM);
        cudaFuncSetAttribute(k_edge2, cudaFuncAttributeMaxDynamicSharedMemorySize, K4_SMEM);
        once = 1;
    }

    k_init<<<2048, 256>>>();
    k_gate<<<(TBL + 8) / 8, 256>>>(fW1, fW2);
    k_edge1<<<296, 256, K1_SMEM>>>(eidx, elen, nattr, ln1g, ln1b, W1, b1, ln2g, ln2b, W2, b2);
    k_sumexp<<<592, 256>>>();
    k_scatter<<<(NE + 7) / 8, 256>>>(eidx);
    k_edge2<<<296, 256, K4_SMEM>>>(eidx, elen, ln3g, ln3b, W3, b3, resp, out);
}